// round 7
// baseline (speedup 1.0000x reference)
#include <cuda_runtime.h>

#define NB 16
#define NC 512
#define NS 128

// Scratch (device globals: allocation-free). Every element is written each
// launch, so no zeroing required.
__device__ float g_ww_part[NB * NS * NS];   // [b][h][w]  partial ww conv sums
__device__ float g_hw_part[NB * NS * 8];    // [b][h][kh] partial hw conv sums (padded 5->8)

// Stage 1: one block per (b, h) row of the image.
//  - reduce x[b, :, h, :] over C=512 with the two 1x1-conv weight vectors
//    (x2_0, x2_1 per w, kept in registers)
//  - width 5-tap stencil with w_ww  -> g_ww_part[b][h][w]
//  - row dot with the 5 w_hw rows   -> g_hw_part[b][h][kh]
__global__ __launch_bounds__(128) void swa_stage1(
    const float* __restrict__ x,       // [B, C, S, S]
    const float* __restrict__ w_conv,  // [2, C] (1x1 kernel squeezed)
    const float* __restrict__ w_ww,    // [2, S, 5]
    const float* __restrict__ w_hw)    // [2, 5, S]
{
    __shared__ float s_w0[NC];
    __shared__ float s_w1[NC];
    __shared__ float s_x20[NS + 4];    // halo of 2 on each side (zero padding)
    __shared__ float s_x21[NS + 4];
    __shared__ float s_red[4 * 5];     // per-warp partials for hw reduction

    const int w = threadIdx.x;         // 0..127
    const int h = blockIdx.x;          // 0..127
    const int b = blockIdx.y;          // 0..15

    // Stage channel weights into shared (broadcast reads in the hot loop).
    for (int i = w; i < NC; i += 128) {
        s_w0[i] = w_conv[i];
        s_w1[i] = w_conv[NC + i];
    }
    if (w < 2) {
        s_x20[w] = 0.f;          s_x21[w] = 0.f;
        s_x20[NS + 2 + w] = 0.f; s_x21[NS + 2 + w] = 0.f;
    }
    __syncthreads();

    // ---- channel reduction: x2_c[b,h,w] = sum_c x[b,c,h,w] * w_conv[c][c'] ----
    const float* xp = x + (((size_t)b * NC) * NS + h) * NS + w;
    float acc0 = 0.f, acc1 = 0.f;
    #pragma unroll 8
    for (int c = 0; c < NC; ++c) {
        float v = xp[(size_t)c * (NS * NS)];   // coalesced 512B per block per c
        acc0 = fmaf(v, s_w0[c], acc0);
        acc1 = fmaf(v, s_w1[c], acc1);
    }

    s_x20[w + 2] = acc0;
    s_x21[w + 2] = acc1;
    __syncthreads();

    // ---- ww branch: 5-tap stencil along w with weights w_ww[c][h][kw] ----
    {
        const float* pw0 = w_ww + h * 5;            // c=0
        const float* pw1 = w_ww + NS * 5 + h * 5;   // c=1
        float sww = 0.f;
        #pragma unroll
        for (int kw = 0; kw < 5; ++kw) {
            // halo index w+kw corresponds to x2 position (w + kw - 2)
            sww = fmaf(s_x20[w + kw], __ldg(pw0 + kw), sww);
            sww = fmaf(s_x21[w + kw], __ldg(pw1 + kw), sww);
        }
        g_ww_part[((size_t)b * NS + h) * NS + w] = sww;
    }

    // ---- hw branch: row dot products with w_hw[c][kh][:], block-reduced ----
    float hv[5];
    #pragma unroll
    for (int kh = 0; kh < 5; ++kh) {
        hv[kh] = acc0 * __ldg(w_hw + kh * NS + w)
               + acc1 * __ldg(w_hw + 5 * NS + kh * NS + w);
    }
    #pragma unroll
    for (int off = 16; off > 0; off >>= 1) {
        #pragma unroll
        for (int kh = 0; kh < 5; ++kh)
            hv[kh] += __shfl_down_sync(0xffffffffu, hv[kh], off);
    }
    const int lane = w & 31, warp = w >> 5;
    if (lane == 0) {
        #pragma unroll
        for (int kh = 0; kh < 5; ++kh) s_red[warp * 5 + kh] = hv[kh];
    }
    __syncthreads();
    if (w < 5) {
        float t = s_red[w] + s_red[5 + w] + s_red[10 + w] + s_red[15 + w];
        g_hw_part[((size_t)b * NS + h) * 8 + w] = t;
    }
}

// Stage 2: one block per batch. Deterministic sum of partials over h,
// linear + sigmoid on both 128-vectors, then write the outer product.
__global__ __launch_bounds__(128) void swa_stage2(
    const float* __restrict__ ww_lin_w,  // [S, S]
    const float* __restrict__ ww_lin_b,  // [S]
    const float* __restrict__ hw_lin_w,  // [S, S]
    const float* __restrict__ hw_lin_b,  // [S]
    float* __restrict__ out)             // [B, S, S]
{
    __shared__ float s_ww[NS];   // raw ww conv output
    __shared__ float s_hw[NS];   // raw hw conv output
    __shared__ float s_wws[NS];  // sigmoid(linear(ww))
    __shared__ float s_hws[NS];  // sigmoid(linear(hw))

    const int t = threadIdx.x;
    const int b = blockIdx.x;

    // ww_raw[t] = sum_h g_ww_part[b][h][t]  (coalesced, fixed order)
    {
        const float* p = g_ww_part + (size_t)b * NS * NS + t;
        float acc = 0.f;
        #pragma unroll 8
        for (int h = 0; h < NS; ++h) acc += p[h * NS];
        s_ww[t] = acc;
    }
    // hw_raw[h] = sum_kh g_hw_part[b][h+kh-2][kh]  (zero padding outside)
    {
        float acc = 0.f;
        #pragma unroll
        for (int kh = 0; kh < 5; ++kh) {
            int hp = t + kh - 2;
            if (hp >= 0 && hp < NS)
                acc += g_hw_part[((size_t)b * NS + hp) * 8 + kh];
        }
        s_hw[t] = acc;
    }
    __syncthreads();

    // Linear (y = W x + b, W row-major [out,in]) + sigmoid, both branches.
    {
        float a = __ldg(ww_lin_b + t);
        const float* wr = ww_lin_w + t * NS;
        #pragma unroll 8
        for (int j = 0; j < NS; ++j) a = fmaf(__ldg(wr + j), s_ww[j], a);
        s_wws[t] = 1.f / (1.f + expf(-a));

        float d = __ldg(hw_lin_b + t);
        const float* hr = hw_lin_w + t * NS;
        #pragma unroll 8
        for (int j = 0; j < NS; ++j) d = fmaf(__ldg(hr + j), s_hw[j], d);
        s_hws[t] = 1.f / (1.f + expf(-d));
    }
    __syncthreads();

    // Outer product: out[b][h][w] = hw_s[h] * ww_s[w]
    const float wwv = s_wws[t];
    float* o = out + (size_t)b * NS * NS;
    #pragma unroll 4
    for (int h = 0; h < NS; ++h)
        o[h * NS + t] = s_hws[h] * wwv;
}

extern "C" void kernel_launch(void* const* d_in, const int* in_sizes, int n_in,
                              void* d_out, int out_size) {
    const float* x        = (const float*)d_in[0];  // [16,512,128,128]
    const float* w_conv   = (const float*)d_in[1];  // [2,512,1,1]
    const float* w_ww     = (const float*)d_in[2];  // [1,2,128,5]
    const float* w_hw     = (const float*)d_in[3];  // [1,2,5,128]
    const float* ww_lin_w = (const float*)d_in[4];  // [128,128]
    const float* ww_lin_b = (const float*)d_in[5];  // [128]
    const float* hw_lin_w = (const float*)d_in[6];  // [128,128]
    const float* hw_lin_b = (const float*)d_in[7];  // [128]
    float* out = (float*)d_out;                     // [16,128,128]

    dim3 grid1(NS, NB);
    swa_stage1<<<grid1, 128>>>(x, w_conv, w_ww, w_hw);
    swa_stage2<<<NB, 128>>>(ww_lin_w, ww_lin_b, hw_lin_w, hw_lin_b, out);
}

// round 8
// speedup vs baseline: 1.0014x; 1.0014x over previous
#include <cuda_runtime.h>

#define NB 16
#define NC 512
#define NS 128

// Scratch (device globals: allocation-free). Every element is written each
// launch, so no zeroing required.
__device__ float g_ww_part[NB * NS * NS];   // [b][h][w]  partial ww conv sums
__device__ float g_hw_part[NB * NS * 8];    // [b][h][kh] partial hw conv sums (padded 5->8)

// Stage 1: one block per (b, h) row of the image.
//  - reduce x[b, :, h, :] over C=512 with the two 1x1-conv weight vectors
//    (x2_0, x2_1 per w, kept in registers)
//  - width 5-tap stencil with w_ww  -> g_ww_part[b][h][w]
//  - row dot with the 5 w_hw rows   -> g_hw_part[b][h][kh]
__global__ __launch_bounds__(128) void swa_stage1(
    const float* __restrict__ x,       // [B, C, S, S]
    const float* __restrict__ w_conv,  // [2, C] (1x1 kernel squeezed)
    const float* __restrict__ w_ww,    // [2, S, 5]
    const float* __restrict__ w_hw)    // [2, 5, S]
{
    __shared__ float s_w0[NC];
    __shared__ float s_w1[NC];
    __shared__ float s_x20[NS + 4];    // halo of 2 on each side (zero padding)
    __shared__ float s_x21[NS + 4];
    __shared__ float s_red[4 * 5];     // per-warp partials for hw reduction

    const int w = threadIdx.x;         // 0..127
    const int h = blockIdx.x;          // 0..127
    const int b = blockIdx.y;          // 0..15

    // Stage channel weights into shared (broadcast reads in the hot loop).
    for (int i = w; i < NC; i += 128) {
        s_w0[i] = w_conv[i];
        s_w1[i] = w_conv[NC + i];
    }
    if (w < 2) {
        s_x20[w] = 0.f;          s_x21[w] = 0.f;
        s_x20[NS + 2 + w] = 0.f; s_x21[NS + 2 + w] = 0.f;
    }
    __syncthreads();

    // ---- channel reduction: x2_c[b,h,w] = sum_c x[b,c,h,w] * w_conv[c][c'] ----
    const float* xp = x + (((size_t)b * NC) * NS + h) * NS + w;
    float acc0 = 0.f, acc1 = 0.f;
    #pragma unroll 8
    for (int c = 0; c < NC; ++c) {
        float v = xp[(size_t)c * (NS * NS)];   // coalesced 512B per block per c
        acc0 = fmaf(v, s_w0[c], acc0);
        acc1 = fmaf(v, s_w1[c], acc1);
    }

    s_x20[w + 2] = acc0;
    s_x21[w + 2] = acc1;
    __syncthreads();

    // ---- ww branch: 5-tap stencil along w with weights w_ww[c][h][kw] ----
    {
        const float* pw0 = w_ww + h * 5;            // c=0
        const float* pw1 = w_ww + NS * 5 + h * 5;   // c=1
        float sww = 0.f;
        #pragma unroll
        for (int kw = 0; kw < 5; ++kw) {
            // halo index w+kw corresponds to x2 position (w + kw - 2)
            sww = fmaf(s_x20[w + kw], __ldg(pw0 + kw), sww);
            sww = fmaf(s_x21[w + kw], __ldg(pw1 + kw), sww);
        }
        g_ww_part[((size_t)b * NS + h) * NS + w] = sww;
    }

    // ---- hw branch: row dot products with w_hw[c][kh][:], block-reduced ----
    float hv[5];
    #pragma unroll
    for (int kh = 0; kh < 5; ++kh) {
        hv[kh] = acc0 * __ldg(w_hw + kh * NS + w)
               + acc1 * __ldg(w_hw + 5 * NS + kh * NS + w);
    }
    #pragma unroll
    for (int off = 16; off > 0; off >>= 1) {
        #pragma unroll
        for (int kh = 0; kh < 5; ++kh)
            hv[kh] += __shfl_down_sync(0xffffffffu, hv[kh], off);
    }
    const int lane = w & 31, warp = w >> 5;
    if (lane == 0) {
        #pragma unroll
        for (int kh = 0; kh < 5; ++kh) s_red[warp * 5 + kh] = hv[kh];
    }
    __syncthreads();
    if (w < 5) {
        float t = s_red[w] + s_red[5 + w] + s_red[10 + w] + s_red[15 + w];
        g_hw_part[((size_t)b * NS + h) * 8 + w] = t;
    }
}

// Stage 2: one block per batch. Deterministic sum of partials over h,
// linear + sigmoid on both 128-vectors, then write the outer product.
__global__ __launch_bounds__(128) void swa_stage2(
    const float* __restrict__ ww_lin_w,  // [S, S]
    const float* __restrict__ ww_lin_b,  // [S]
    const float* __restrict__ hw_lin_w,  // [S, S]
    const float* __restrict__ hw_lin_b,  // [S]
    float* __restrict__ out)             // [B, S, S]
{
    __shared__ float s_ww[NS];   // raw ww conv output
    __shared__ float s_hw[NS];   // raw hw conv output
    __shared__ float s_wws[NS];  // sigmoid(linear(ww))
    __shared__ float s_hws[NS];  // sigmoid(linear(hw))

    const int t = threadIdx.x;
    const int b = blockIdx.x;

    // ww_raw[t] = sum_h g_ww_part[b][h][t]  (coalesced, fixed order)
    {
        const float* p = g_ww_part + (size_t)b * NS * NS + t;
        float acc = 0.f;
        #pragma unroll 8
        for (int h = 0; h < NS; ++h) acc += p[h * NS];
        s_ww[t] = acc;
    }
    // hw_raw[h] = sum_kh g_hw_part[b][h+kh-2][kh]  (zero padding outside)
    {
        float acc = 0.f;
        #pragma unroll
        for (int kh = 0; kh < 5; ++kh) {
            int hp = t + kh - 2;
            if (hp >= 0 && hp < NS)
                acc += g_hw_part[((size_t)b * NS + hp) * 8 + kh];
        }
        s_hw[t] = acc;
    }
    __syncthreads();

    // Linear (y = W x + b, W row-major [out,in]) + sigmoid, both branches.
    {
        float a = __ldg(ww_lin_b + t);
        const float* wr = ww_lin_w + t * NS;
        #pragma unroll 8
        for (int j = 0; j < NS; ++j) a = fmaf(__ldg(wr + j), s_ww[j], a);
        s_wws[t] = 1.f / (1.f + expf(-a));

        float d = __ldg(hw_lin_b + t);
        const float* hr = hw_lin_w + t * NS;
        #pragma unroll 8
        for (int j = 0; j < NS; ++j) d = fmaf(__ldg(hr + j), s_hw[j], d);
        s_hws[t] = 1.f / (1.f + expf(-d));
    }
    __syncthreads();

    // Outer product: out[b][h][w] = hw_s[h] * ww_s[w]
    const float wwv = s_wws[t];
    float* o = out + (size_t)b * NS * NS;
    #pragma unroll 4
    for (int h = 0; h < NS; ++h)
        o[h * NS + t] = s_hws[h] * wwv;
}

extern "C" void kernel_launch(void* const* d_in, const int* in_sizes, int n_in,
                              void* d_out, int out_size) {
    const float* x        = (const float*)d_in[0];  // [16,512,128,128]
    const float* w_conv   = (const float*)d_in[1];  // [2,512,1,1]
    const float* w_ww     = (const float*)d_in[2];  // [1,2,128,5]
    const float* w_hw     = (const float*)d_in[3];  // [1,2,5,128]
    const float* ww_lin_w = (const float*)d_in[4];  // [128,128]
    const float* ww_lin_b = (const float*)d_in[5];  // [128]
    const float* hw_lin_w = (const float*)d_in[6];  // [128,128]
    const float* hw_lin_b = (const float*)d_in[7];  // [128]
    float* out = (float*)d_out;                     // [16,128,128]

    dim3 grid1(NS, NB);
    swa_stage1<<<grid1, 128>>>(x, w_conv, w_ww, w_hw);
    swa_stage2<<<NB, 128>>>(ww_lin_w, ww_lin_b, hw_lin_w, hw_lin_b, out);
}

// round 9
// speedup vs baseline: 1.0062x; 1.0048x over previous
#include <cuda_runtime.h>

#define NB 16
#define NC 512
#define NS 128

// Scratch (device globals: allocation-free). Every element is written each
// launch, so no zeroing required.
__device__ float g_ww_part[NB * NS * NS];   // [b][h][w]  partial ww conv sums
__device__ float g_hw_part[NB * NS * 8];    // [b][h][kh] partial hw conv sums (padded 5->8)

// Stage 1: one block per (b, h) row of the image.
//  - reduce x[b, :, h, :] over C=512 with the two 1x1-conv weight vectors
//    (x2_0, x2_1 per w, kept in registers)
//  - width 5-tap stencil with w_ww  -> g_ww_part[b][h][w]
//  - row dot with the 5 w_hw rows   -> g_hw_part[b][h][kh]
__global__ __launch_bounds__(128) void swa_stage1(
    const float* __restrict__ x,       // [B, C, S, S]
    const float* __restrict__ w_conv,  // [2, C] (1x1 kernel squeezed)
    const float* __restrict__ w_ww,    // [2, S, 5]
    const float* __restrict__ w_hw)    // [2, 5, S]
{
    __shared__ float s_w0[NC];
    __shared__ float s_w1[NC];
    __shared__ float s_x20[NS + 4];    // halo of 2 on each side (zero padding)
    __shared__ float s_x21[NS + 4];
    __shared__ float s_red[4 * 5];     // per-warp partials for hw reduction

    const int w = threadIdx.x;         // 0..127
    const int h = blockIdx.x;          // 0..127
    const int b = blockIdx.y;          // 0..15

    // Stage channel weights into shared (broadcast reads in the hot loop).
    for (int i = w; i < NC; i += 128) {
        s_w0[i] = w_conv[i];
        s_w1[i] = w_conv[NC + i];
    }
    if (w < 2) {
        s_x20[w] = 0.f;          s_x21[w] = 0.f;
        s_x20[NS + 2 + w] = 0.f; s_x21[NS + 2 + w] = 0.f;
    }
    __syncthreads();

    // ---- channel reduction: x2_c[b,h,w] = sum_c x[b,c,h,w] * w_conv[c][c'] ----
    const float* xp = x + (((size_t)b * NC) * NS + h) * NS + w;
    float acc0 = 0.f, acc1 = 0.f;
    #pragma unroll 8
    for (int c = 0; c < NC; ++c) {
        float v = xp[(size_t)c * (NS * NS)];   // coalesced 512B per block per c
        acc0 = fmaf(v, s_w0[c], acc0);
        acc1 = fmaf(v, s_w1[c], acc1);
    }

    s_x20[w + 2] = acc0;
    s_x21[w + 2] = acc1;
    __syncthreads();

    // ---- ww branch: 5-tap stencil along w with weights w_ww[c][h][kw] ----
    {
        const float* pw0 = w_ww + h * 5;            // c=0
        const float* pw1 = w_ww + NS * 5 + h * 5;   // c=1
        float sww = 0.f;
        #pragma unroll
        for (int kw = 0; kw < 5; ++kw) {
            // halo index w+kw corresponds to x2 position (w + kw - 2)
            sww = fmaf(s_x20[w + kw], __ldg(pw0 + kw), sww);
            sww = fmaf(s_x21[w + kw], __ldg(pw1 + kw), sww);
        }
        g_ww_part[((size_t)b * NS + h) * NS + w] = sww;
    }

    // ---- hw branch: row dot products with w_hw[c][kh][:], block-reduced ----
    float hv[5];
    #pragma unroll
    for (int kh = 0; kh < 5; ++kh) {
        hv[kh] = acc0 * __ldg(w_hw + kh * NS + w)
               + acc1 * __ldg(w_hw + 5 * NS + kh * NS + w);
    }
    #pragma unroll
    for (int off = 16; off > 0; off >>= 1) {
        #pragma unroll
        for (int kh = 0; kh < 5; ++kh)
            hv[kh] += __shfl_down_sync(0xffffffffu, hv[kh], off);
    }
    const int lane = w & 31, warp = w >> 5;
    if (lane == 0) {
        #pragma unroll
        for (int kh = 0; kh < 5; ++kh) s_red[warp * 5 + kh] = hv[kh];
    }
    __syncthreads();
    if (w < 5) {
        float t = s_red[w] + s_red[5 + w] + s_red[10 + w] + s_red[15 + w];
        g_hw_part[((size_t)b * NS + h) * 8 + w] = t;
    }
}

// Stage 2: one block per batch. Deterministic sum of partials over h,
// linear + sigmoid on both 128-vectors, then write the outer product.
__global__ __launch_bounds__(128) void swa_stage2(
    const float* __restrict__ ww_lin_w,  // [S, S]
    const float* __restrict__ ww_lin_b,  // [S]
    const float* __restrict__ hw_lin_w,  // [S, S]
    const float* __restrict__ hw_lin_b,  // [S]
    float* __restrict__ out)             // [B, S, S]
{
    __shared__ float s_ww[NS];   // raw ww conv output
    __shared__ float s_hw[NS];   // raw hw conv output
    __shared__ float s_wws[NS];  // sigmoid(linear(ww))
    __shared__ float s_hws[NS];  // sigmoid(linear(hw))

    const int t = threadIdx.x;
    const int b = blockIdx.x;

    // ww_raw[t] = sum_h g_ww_part[b][h][t]  (coalesced, fixed order)
    {
        const float* p = g_ww_part + (size_t)b * NS * NS + t;
        float acc = 0.f;
        #pragma unroll 8
        for (int h = 0; h < NS; ++h) acc += p[h * NS];
        s_ww[t] = acc;
    }
    // hw_raw[h] = sum_kh g_hw_part[b][h+kh-2][kh]  (zero padding outside)
    {
        float acc = 0.f;
        #pragma unroll
        for (int kh = 0; kh < 5; ++kh) {
            int hp = t + kh - 2;
            if (hp >= 0 && hp < NS)
                acc += g_hw_part[((size_t)b * NS + hp) * 8 + kh];
        }
        s_hw[t] = acc;
    }
    __syncthreads();

    // Linear (y = W x + b, W row-major [out,in]) + sigmoid, both branches.
    {
        float a = __ldg(ww_lin_b + t);
        const float* wr = ww_lin_w + t * NS;
        #pragma unroll 8
        for (int j = 0; j < NS; ++j) a = fmaf(__ldg(wr + j), s_ww[j], a);
        s_wws[t] = 1.f / (1.f + expf(-a));

        float d = __ldg(hw_lin_b + t);
        const float* hr = hw_lin_w + t * NS;
        #pragma unroll 8
        for (int j = 0; j < NS; ++j) d = fmaf(__ldg(hr + j), s_hw[j], d);
        s_hws[t] = 1.f / (1.f + expf(-d));
    }
    __syncthreads();

    // Outer product: out[b][h][w] = hw_s[h] * ww_s[w]
    const float wwv = s_wws[t];
    float* o = out + (size_t)b * NS * NS;
    #pragma unroll 4
    for (int h = 0; h < NS; ++h)
        o[h * NS + t] = s_hws[h] * wwv;
}

extern "C" void kernel_launch(void* const* d_in, const int* in_sizes, int n_in,
                              void* d_out, int out_size) {
    const float* x        = (const float*)d_in[0];  // [16,512,128,128]
    const float* w_conv   = (const float*)d_in[1];  // [2,512,1,1]
    const float* w_ww     = (const float*)d_in[2];  // [1,2,128,5]
    const float* w_hw     = (const float*)d_in[3];  // [1,2,5,128]
    const float* ww_lin_w = (const float*)d_in[4];  // [128,128]
    const float* ww_lin_b = (const float*)d_in[5];  // [128]
    const float* hw_lin_w = (const float*)d_in[6];  // [128,128]
    const float* hw_lin_b = (const float*)d_in[7];  // [128]
    float* out = (float*)d_out;                     // [16,128,128]

    dim3 grid1(NS, NB);
    swa_stage1<<<grid1, 128>>>(x, w_conv, w_ww, w_hw);
    swa_stage2<<<NB, 128>>>(ww_lin_w, ww_lin_b, hw_lin_w, hw_lin_b, out);
}

// round 10
// speedup vs baseline: 1.0135x; 1.0073x over previous
#include <cuda_runtime.h>

#define NB 16
#define NC 512
#define NS 128

// Scratch (device globals: allocation-free). Every element is written each
// launch, so no zeroing required.
__device__ float g_ww_part[NB * NS * NS];   // [b][h][w]  partial ww conv sums
__device__ float g_hw_part[NB * NS * 8];    // [b][h][kh] partial hw conv sums (padded 5->8)

// Stage 1: one block per (b, h) row of the image.
//  - reduce x[b, :, h, :] over C=512 with the two 1x1-conv weight vectors
//    (x2_0, x2_1 per w, kept in registers)
//  - width 5-tap stencil with w_ww  -> g_ww_part[b][h][w]
//  - row dot with the 5 w_hw rows   -> g_hw_part[b][h][kh]
__global__ __launch_bounds__(128) void swa_stage1(
    const float* __restrict__ x,       // [B, C, S, S]
    const float* __restrict__ w_conv,  // [2, C] (1x1 kernel squeezed)
    const float* __restrict__ w_ww,    // [2, S, 5]
    const float* __restrict__ w_hw)    // [2, 5, S]
{
    __shared__ float s_w0[NC];
    __shared__ float s_w1[NC];
    __shared__ float s_x20[NS + 4];    // halo of 2 on each side (zero padding)
    __shared__ float s_x21[NS + 4];
    __shared__ float s_red[4 * 5];     // per-warp partials for hw reduction

    const int w = threadIdx.x;         // 0..127
    const int h = blockIdx.x;          // 0..127
    const int b = blockIdx.y;          // 0..15

    // Stage channel weights into shared (broadcast reads in the hot loop).
    for (int i = w; i < NC; i += 128) {
        s_w0[i] = w_conv[i];
        s_w1[i] = w_conv[NC + i];
    }
    if (w < 2) {
        s_x20[w] = 0.f;          s_x21[w] = 0.f;
        s_x20[NS + 2 + w] = 0.f; s_x21[NS + 2 + w] = 0.f;
    }
    __syncthreads();

    // ---- channel reduction: x2_c[b,h,w] = sum_c x[b,c,h,w] * w_conv[c][c'] ----
    const float* xp = x + (((size_t)b * NC) * NS + h) * NS + w;
    float acc0 = 0.f, acc1 = 0.f;
    #pragma unroll 8
    for (int c = 0; c < NC; ++c) {
        float v = xp[(size_t)c * (NS * NS)];   // coalesced 512B per block per c
        acc0 = fmaf(v, s_w0[c], acc0);
        acc1 = fmaf(v, s_w1[c], acc1);
    }

    s_x20[w + 2] = acc0;
    s_x21[w + 2] = acc1;
    __syncthreads();

    // ---- ww branch: 5-tap stencil along w with weights w_ww[c][h][kw] ----
    {
        const float* pw0 = w_ww + h * 5;            // c=0
        const float* pw1 = w_ww + NS * 5 + h * 5;   // c=1
        float sww = 0.f;
        #pragma unroll
        for (int kw = 0; kw < 5; ++kw) {
            // halo index w+kw corresponds to x2 position (w + kw - 2)
            sww = fmaf(s_x20[w + kw], __ldg(pw0 + kw), sww);
            sww = fmaf(s_x21[w + kw], __ldg(pw1 + kw), sww);
        }
        g_ww_part[((size_t)b * NS + h) * NS + w] = sww;
    }

    // ---- hw branch: row dot products with w_hw[c][kh][:], block-reduced ----
    float hv[5];
    #pragma unroll
    for (int kh = 0; kh < 5; ++kh) {
        hv[kh] = acc0 * __ldg(w_hw + kh * NS + w)
               + acc1 * __ldg(w_hw + 5 * NS + kh * NS + w);
    }
    #pragma unroll
    for (int off = 16; off > 0; off >>= 1) {
        #pragma unroll
        for (int kh = 0; kh < 5; ++kh)
            hv[kh] += __shfl_down_sync(0xffffffffu, hv[kh], off);
    }
    const int lane = w & 31, warp = w >> 5;
    if (lane == 0) {
        #pragma unroll
        for (int kh = 0; kh < 5; ++kh) s_red[warp * 5 + kh] = hv[kh];
    }
    __syncthreads();
    if (w < 5) {
        float t = s_red[w] + s_red[5 + w] + s_red[10 + w] + s_red[15 + w];
        g_hw_part[((size_t)b * NS + h) * 8 + w] = t;
    }
}

// Stage 2: one block per batch. Deterministic sum of partials over h,
// linear + sigmoid on both 128-vectors, then write the outer product.
__global__ __launch_bounds__(128) void swa_stage2(
    const float* __restrict__ ww_lin_w,  // [S, S]
    const float* __restrict__ ww_lin_b,  // [S]
    const float* __restrict__ hw_lin_w,  // [S, S]
    const float* __restrict__ hw_lin_b,  // [S]
    float* __restrict__ out)             // [B, S, S]
{
    __shared__ float s_ww[NS];   // raw ww conv output
    __shared__ float s_hw[NS];   // raw hw conv output
    __shared__ float s_wws[NS];  // sigmoid(linear(ww))
    __shared__ float s_hws[NS];  // sigmoid(linear(hw))

    const int t = threadIdx.x;
    const int b = blockIdx.x;

    // ww_raw[t] = sum_h g_ww_part[b][h][t]  (coalesced, fixed order)
    {
        const float* p = g_ww_part + (size_t)b * NS * NS + t;
        float acc = 0.f;
        #pragma unroll 8
        for (int h = 0; h < NS; ++h) acc += p[h * NS];
        s_ww[t] = acc;
    }
    // hw_raw[h] = sum_kh g_hw_part[b][h+kh-2][kh]  (zero padding outside)
    {
        float acc = 0.f;
        #pragma unroll
        for (int kh = 0; kh < 5; ++kh) {
            int hp = t + kh - 2;
            if (hp >= 0 && hp < NS)
                acc += g_hw_part[((size_t)b * NS + hp) * 8 + kh];
        }
        s_hw[t] = acc;
    }
    __syncthreads();

    // Linear (y = W x + b, W row-major [out,in]) + sigmoid, both branches.
    {
        float a = __ldg(ww_lin_b + t);
        const float* wr = ww_lin_w + t * NS;
        #pragma unroll 8
        for (int j = 0; j < NS; ++j) a = fmaf(__ldg(wr + j), s_ww[j], a);
        s_wws[t] = 1.f / (1.f + expf(-a));

        float d = __ldg(hw_lin_b + t);
        const float* hr = hw_lin_w + t * NS;
        #pragma unroll 8
        for (int j = 0; j < NS; ++j) d = fmaf(__ldg(hr + j), s_hw[j], d);
        s_hws[t] = 1.f / (1.f + expf(-d));
    }
    __syncthreads();

    // Outer product: out[b][h][w] = hw_s[h] * ww_s[w]
    const float wwv = s_wws[t];
    float* o = out + (size_t)b * NS * NS;
    #pragma unroll 4
    for (int h = 0; h < NS; ++h)
        o[h * NS + t] = s_hws[h] * wwv;
}

extern "C" void kernel_launch(void* const* d_in, const int* in_sizes, int n_in,
                              void* d_out, int out_size) {
    const float* x        = (const float*)d_in[0];  // [16,512,128,128]
    const float* w_conv   = (const float*)d_in[1];  // [2,512,1,1]
    const float* w_ww     = (const float*)d_in[2];  // [1,2,128,5]
    const float* w_hw     = (const float*)d_in[3];  // [1,2,5,128]
    const float* ww_lin_w = (const float*)d_in[4];  // [128,128]
    const float* ww_lin_b = (const float*)d_in[5];  // [128]
    const float* hw_lin_w = (const float*)d_in[6];  // [128,128]
    const float* hw_lin_b = (const float*)d_in[7];  // [128]
    float* out = (float*)d_out;                     // [16,128,128]

    dim3 grid1(NS, NB);
    swa_stage1<<<grid1, 128>>>(x, w_conv, w_ww, w_hw);
    swa_stage2<<<NB, 128>>>(ww_lin_w, ww_lin_b, hw_lin_w, hw_lin_b, out);
}